// round 13
// baseline (speedup 1.0000x reference)
#include <cuda_runtime.h>
#include <cuda_bf16.h>
#include <cuda_fp16.h>
#include <cstdint>

#define BB 4
#define HH 16
#define SS 2048
#define DD 64

#define TM 64          // q rows per CTA
#define KT 64          // keys per tile
#define NTILES (SS / KT)
#define NTHREADS 256
#define KST 72         // smem row stride in halves (144B): conflict-free frag loads

#define TILE_B  (KT * KST * 2)     // 9216 bytes per part
#define NPART 2                    // Kh, Vh (both fp16)
#define BUF_B   (NPART * TILE_B)   // 18432
#define NBUF 3
#define ZBUF_OFF (NBUF * BUF_B)    // 55296
#define INVZ_OFF (ZBUF_OFF + 512)
#define SMEM_TOTAL (INVZ_OFF + 256)

#define NELEM (BB * HH * SS * DD)  // 8388608
#define MWORDS (BB * SS * (SS / 32))  // 524288 uint32

__device__ uint16_t g_kh[NELEM];
__device__ uint16_t g_vh[NELEM];
__device__ uint32_t g_mbits[MWORDS];
__device__ uint16_t g_e[(size_t)BB * HH * SS * SS];   // fp16 unnormalized probs (0.5 GB)

// ---------------- fast 2^y via MUFU.EX2 (1 instr) ----------------
__device__ __forceinline__ float fexp2f(float y) {
    float r;
    asm("ex2.approx.f32 %0, %1;" : "=f"(r) : "f"(y));
    return r;
}
#define L2E  1.4426950408889634f
#define SHL2 11.541560327111707f   // 8*log2(e):  exp(s-8) = 2^(s*L2E - SHL2)

// ---------------- wrappers ----------------
__device__ __forceinline__ void mma16816h(float* c, const uint32_t* a, uint32_t b0, uint32_t b1) {
    asm volatile(
        "mma.sync.aligned.m16n8k16.row.col.f32.f16.f16.f32 "
        "{%0,%1,%2,%3},{%4,%5,%6,%7},{%8,%9},{%0,%1,%2,%3};"
        : "+f"(c[0]), "+f"(c[1]), "+f"(c[2]), "+f"(c[3])
        : "r"(a[0]), "r"(a[1]), "r"(a[2]), "r"(a[3]), "r"(b0), "r"(b1));
}
__device__ __forceinline__ void ldsm_x2_trans(uint32_t& r0, uint32_t& r1, uint32_t addr) {
    asm volatile("ldmatrix.sync.aligned.m8n8.x2.trans.shared.b16 {%0,%1}, [%2];"
                 : "=r"(r0), "=r"(r1) : "r"(addr));
}
__device__ __forceinline__ void ldsm_x4(uint32_t& r0, uint32_t& r1, uint32_t& r2, uint32_t& r3,
                                        uint32_t addr) {
    asm volatile("ldmatrix.sync.aligned.m8n8.x4.shared.b16 {%0,%1,%2,%3}, [%4];"
                 : "=r"(r0), "=r"(r1), "=r"(r2), "=r"(r3) : "r"(addr));
}
__device__ __forceinline__ uint32_t pack_f16(float x, float y) {
    __half2 h = __floats2half2_rn(x, y);
    return *(uint32_t*)&h;
}

__device__ __forceinline__ void cp16(uint32_t dst, const void* src) {
    asm volatile("cp.async.cg.shared.global [%0], [%1], 16;" :: "r"(dst), "l"(src));
}
#define CP_COMMIT() asm volatile("cp.async.commit_group;" ::: "memory")
#define CP_WAIT(n)  asm volatile("cp.async.wait_group %0;" :: "n"(n) : "memory")

// stage one tile (2 parts) via cp.async: 4 x 16B per thread
__device__ __forceinline__ void stage_async(uint32_t sbuf, size_t base, int tid) {
    const uint16_t* srcs[NPART] = {g_kh + base, g_vh + base};
    #pragma unroll
    for (int part = 0; part < NPART; ++part) {
        uint32_t dpart = sbuf + part * TILE_B;
        #pragma unroll
        for (int it = 0; it < 2; ++it) {
            int idx = tid + it * NTHREADS;     // 0..511
            int row = idx >> 3;
            int seg = idx & 7;
            cp16(dpart + row * 144 + seg * 16, srcs[part] + row * 64 + seg * 8);
        }
    }
}

// ---------------- prepack: f32 K,V -> fp16 ----------------
__global__ __launch_bounds__(256)
void prepack_kernel(const float* __restrict__ k, const float* __restrict__ v)
{
    size_t i = (size_t)blockIdx.x * 256 + threadIdx.x;   // float4 index
    float4 x = ((const float4*)k)[i];
    ((uint2*)g_kh)[i] = make_uint2(pack_f16(x.x, x.y), pack_f16(x.z, x.w));
    float4 y = ((const float4*)v)[i];
    ((uint2*)g_vh)[i] = make_uint2(pack_f16(y.x, y.y), pack_f16(y.z, y.w));
}

// ---------------- maskpack: int32 mask -> bitmask ----------------
__global__ __launch_bounds__(256)
void maskpack_kernel(const int* __restrict__ mask)
{
    size_t i = (size_t)blockIdx.x * 256 + threadIdx.x;
    int m = mask[i];
    uint32_t bits = __ballot_sync(0xffffffffu, m != 0);
    if ((threadIdx.x & 31) == 0) g_mbits[i >> 5] = bits;
}

__global__ __launch_bounds__(NTHREADS, 2)
void psdpa_mma_kernel(const float* __restrict__ q,
                      float* __restrict__ out,
                      float* __restrict__ attn)
{
    extern __shared__ __align__(16) char dsm[];
    float* Zbuf  = (float*)(dsm + ZBUF_OFF);
    float* invZs = (float*)(dsm + INVZ_OFF);
    const uint32_t sbase = (uint32_t)__cvta_generic_to_shared(dsm);

    const int tid  = threadIdx.x;
    const int w    = tid >> 5;
    const int lane = tid & 31;
    const int wr   = w & 3;        // row group (16 rows each)
    const int wc   = w >> 2;       // key-column half (32 keys each)
    const int g    = lane >> 2;
    const int j2   = (lane & 3) << 1;

    const int bh = blockIdx.y;
    const int b  = bh >> 4;
    const int q0 = blockIdx.x * TM;

    const float* qbase = q + ((size_t)bh * SS + q0) * DD;
    const size_t kvbase = (size_t)bh * SS * DD;

    // ---- Q fragments (scaled 1/8), fp16; f32 staging in buffer region ----
    uint32_t qh[4][4];
    {
        float* Qtmp = (float*)dsm;   // 16 KB
        const float4* qg = (const float4*)qbase;
        #pragma unroll
        for (int it = 0; it < 4; ++it) {
            int idx = tid + it * NTHREADS;
            int row = idx >> 4;
            int d4  = (idx & 15) << 2;
            float4 x = qg[idx];
            x.x *= 0.125f; x.y *= 0.125f; x.z *= 0.125f; x.w *= 0.125f;
            *(float4*)(Qtmp + row * DD + d4) = x;
        }
        __syncthreads();
        const int r0 = wr * 16 + g, r1 = r0 + 8;
        #pragma unroll
        for (int ks = 0; ks < 4; ++ks) {
            int d0 = ks * 16 + j2, d1 = d0 + 8;
            float2 x0 = *(float2*)(Qtmp + r0 * DD + d0);
            float2 x1 = *(float2*)(Qtmp + r1 * DD + d0);
            float2 x2 = *(float2*)(Qtmp + r0 * DD + d1);
            float2 x3 = *(float2*)(Qtmp + r1 * DD + d1);
            qh[ks][0] = pack_f16(x0.x, x0.y);
            qh[ks][1] = pack_f16(x1.x, x1.y);
            qh[ks][2] = pack_f16(x2.x, x2.y);
            qh[ks][3] = pack_f16(x3.x, x3.y);
        }
        __syncthreads();   // Qtmp region free before cp.async writes
    }

    const int qrow0 = q0 + wr * 16 + g;
    const int qrow8 = qrow0 + 8;
    const uint32_t* mb0 = g_mbits + ((size_t)b * SS + qrow0) * (SS / 32);
    const uint32_t* mb8 = g_mbits + ((size_t)b * SS + qrow8) * (SS / 32);
    uint16_t* erow0 = g_e + ((size_t)bh * SS + qrow0) * SS;
    uint16_t* erow8 = g_e + ((size_t)bh * SS + qrow8) * SS;

    // V frag (ldmatrix trans) per-lane offset within a part
    const int lkey = lane & 15;
    const uint32_t vfrag_off = ((wc * 32 + lkey) * KST) * 2;
    // K frag (ldmatrix non-trans) per-lane offset within a part
    const uint32_t kfrag_off =
        (((wc * 32 + (lane >> 4) * 8 + (lane & 7)) * KST) + ((lane >> 3) & 1) * 8) * 2;

    // ---- prologue: issue tiles 0 and 1 ----
    stage_async(sbase + 0 * BUF_B, kvbase + 0 * (size_t)KT * DD, tid);
    CP_COMMIT();
    stage_async(sbase + 1 * BUF_B, kvbase + 1 * (size_t)KT * DD, tid);
    CP_COMMIT();

    float O[8][4];
    #pragma unroll
    for (int i = 0; i < 8; ++i)
        #pragma unroll
        for (int c = 0; c < 4; ++c) O[i][c] = 0.0f;
    float Zp0 = 0.0f, Zp1 = 0.0f;

    int cur = 0;
    for (int t = 0; t < NTILES; ++t) {
        // prefetch this tile's mask bits (1 word covers this warp's 32 keys)
        uint32_t mw0 = mb0[2 * t + wc];
        uint32_t mw8 = mb8[2 * t + wc];

        if (t + 1 < NTILES) { CP_WAIT(1); } else { CP_WAIT(0); }
        __syncthreads();
        if (t + 2 < NTILES) {
            int nb = cur + 2; if (nb >= NBUF) nb -= NBUF;
            stage_async(sbase + nb * BUF_B, kvbase + (size_t)(t + 2) * KT * DD, tid);
            CP_COMMIT();
        }

        const uint32_t kh_b = sbase + cur * BUF_B + kfrag_off;
        const uint32_t vh_base = sbase + cur * BUF_B + TILE_B + vfrag_off;

        // ---------------- QK^T (fp16) : S[4 n8][4] over 32 keys ----------------
        float S[4][4];
        #pragma unroll
        for (int i = 0; i < 4; ++i)
            #pragma unroll
            for (int c = 0; c < 4; ++c) S[i][c] = 0.0f;

        #pragma unroll
        for (int ks = 0; ks < 4; ++ks) {
            uint32_t bh0[4], bh1[4];
            ldsm_x4(bh0[0], bh1[0], bh0[1], bh1[1], kh_b + ks * 32);
            ldsm_x4(bh0[2], bh1[2], bh0[3], bh1[3], kh_b + ks * 32 + 16 * KST * 2);
            #pragma unroll
            for (int n8 = 0; n8 < 4; ++n8) mma16816h(S[n8], qh[ks], bh0[n8], bh1[n8]);
        }

        // ------------ mask + exp (MUFU) + fp16 e store + Z + P frags -----------
        uint32_t phi[2][4];
        #pragma unroll
        for (int gi = 0; gi < 4; ++gi) {
            int cb = t * KT + wc * 32 + gi * 8 + j2;
            int bit = gi * 8 + j2;
            float e0 = ((mw0 >> bit) & 1)       ? fexp2f(fmaf(S[gi][0], L2E, -SHL2)) : 0.0f;
            float e1 = ((mw0 >> (bit + 1)) & 1) ? fexp2f(fmaf(S[gi][1], L2E, -SHL2)) : 0.0f;
            float e2 = ((mw8 >> bit) & 1)       ? fexp2f(fmaf(S[gi][2], L2E, -SHL2)) : 0.0f;
            float e3 = ((mw8 >> (bit + 1)) & 1) ? fexp2f(fmaf(S[gi][3], L2E, -SHL2)) : 0.0f;
            Zp0 += e0 + e1;
            Zp1 += e2 + e3;
            int kc = gi >> 1, hh = (gi & 1) << 1;
            uint32_t p01 = pack_f16(e0, e1);
            uint32_t p23 = pack_f16(e2, e3);
            phi[kc][hh + 0] = p01;
            phi[kc][hh + 1] = p23;
            *(uint32_t*)(erow0 + cb) = p01;     // fp16 e scratch (half the bytes)
            *(uint32_t*)(erow8 + cb) = p23;
        }

        // ---------------- P @ V (fp16 x fp16) : O[8 dn8][4] ----------------
        #pragma unroll
        for (int kc = 0; kc < 2; ++kc) {
            #pragma unroll
            for (int dn8 = 0; dn8 < 8; ++dn8) {
                uint32_t vh0, vh1;
                ldsm_x2_trans(vh0, vh1, vh_base + (kc * 16 * KST + dn8 * 8) * 2);
                mma16816h(O[dn8], phi[kc], vh0, vh1);
            }
        }

        if (++cur == NBUF) cur = 0;
    }

    // ---------------- epilogue: Z reduce ----------------
    Zp0 += __shfl_xor_sync(0xffffffffu, Zp0, 1);
    Zp0 += __shfl_xor_sync(0xffffffffu, Zp0, 2);
    Zp1 += __shfl_xor_sync(0xffffffffu, Zp1, 1);
    Zp1 += __shfl_xor_sync(0xffffffffu, Zp1, 2);
    __syncthreads();              // all tiles done using smem; e writes visible
    if ((lane & 3) == 0) {
        Zbuf[wc * TM + wr * 16 + g]     = Zp0;
        Zbuf[wc * TM + wr * 16 + g + 8] = Zp1;
    }
    __syncthreads();
    if (tid < TM) {
        invZs[tid] = 1.0f / (Zbuf[tid] + Zbuf[TM + tid]);
    }

    // ---------------- O reduce + write out ----------------
    float* Obuf = (float*)dsm;    // [64][68] f32 = 17408 B
    const int r0 = wr * 16 + g, r1 = r0 + 8;
    if (wc == 0) {
        #pragma unroll
        for (int dn8 = 0; dn8 < 8; ++dn8) {
            *(float2*)(Obuf + r0 * 68 + dn8 * 8 + j2) = make_float2(O[dn8][0], O[dn8][1]);
            *(float2*)(Obuf + r1 * 68 + dn8 * 8 + j2) = make_float2(O[dn8][2], O[dn8][3]);
        }
    }
    __syncthreads();
    if (wc == 1) {
        #pragma unroll
        for (int dn8 = 0; dn8 < 8; ++dn8) {
            float2* p0 = (float2*)(Obuf + r0 * 68 + dn8 * 8 + j2);
            float2* p1 = (float2*)(Obuf + r1 * 68 + dn8 * 8 + j2);
            float2 a0 = *p0, a1 = *p1;
            a0.x += O[dn8][0]; a0.y += O[dn8][1];
            a1.x += O[dn8][2]; a1.y += O[dn8][3];
            *p0 = a0; *p1 = a1;
        }
    }
    __syncthreads();
    {
        int row = tid >> 2;
        int dq  = (tid & 3) * 16;
        float iz = invZs[row];
        float* orow = out + ((size_t)bh * SS + q0 + row) * DD + dq;
        #pragma unroll
        for (int i = 0; i < 4; ++i) {
            float4 x = *(float4*)(Obuf + row * 68 + dq + i * 4);
            x.x *= iz; x.y *= iz; x.z *= iz; x.w *= iz;
            *(float4*)(orow + i * 4) = x;
        }
    }

    // ------- fused attn normalization: read fp16 e (L2-hot), write f32 once ----
    {
        const uint16_t* e_base = g_e + ((size_t)bh * SS + q0) * SS;
        float* attn_base = attn + ((size_t)bh * SS + q0) * SS;
        #pragma unroll
        for (int rr = 0; rr < 8; ++rr) {
            int row = w + 8 * rr;
            float iz = invZs[row];
            const uint2* e2 = (const uint2*)(e_base + (size_t)row * SS);  // 512 per row
            float4* a4 = (float4*)(attn_base + (size_t)row * SS);
            #pragma unroll 4
            for (int i = 0; i < 16; ++i) {
                int idx = lane + 32 * i;
                uint2 ev = e2[idx];
                float2 f0 = __half22float2(*(__half2*)&ev.x);
                float2 f1 = __half22float2(*(__half2*)&ev.y);
                a4[idx] = make_float4(f0.x * iz, f0.y * iz, f1.x * iz, f1.y * iz);
            }
        }
    }
}

extern "C" void kernel_launch(void* const* d_in, const int* in_sizes, int n_in,
                              void* d_out, int out_size)
{
    const float* q    = (const float*)d_in[0];
    const float* k    = (const float*)d_in[1];
    const float* v    = (const float*)d_in[2];
    const int*   mask = (const int*)d_in[3];

    float* out  = (float*)d_out;
    float* attn = out + (size_t)BB * HH * SS * DD;

    static bool configured = false;
    if (!configured) {
        cudaFuncSetAttribute(psdpa_mma_kernel,
                             cudaFuncAttributeMaxDynamicSharedMemorySize, SMEM_TOTAL);
        configured = true;
    }

    prepack_kernel<<<NELEM / 4 / 256, 256>>>(k, v);
    maskpack_kernel<<<(BB * SS * SS) / 256, 256>>>(mask);

    dim3 grid1(SS / TM, BB * HH);
    psdpa_mma_kernel<<<grid1, NTHREADS, SMEM_TOTAL>>>(q, out, attn);
}

// round 14
// speedup vs baseline: 1.3265x; 1.3265x over previous
#include <cuda_runtime.h>
#include <cuda_bf16.h>
#include <cuda_fp16.h>
#include <cstdint>

#define BB 4
#define HH 16
#define SS 2048
#define DD 64

#define TM 64          // q rows per CTA
#define KT 64          // keys per tile
#define NTILES (SS / KT)
#define NTHREADS 256
#define KST 72         // smem row stride in halves (144B): conflict-free frag loads

#define TILE_B  (KT * KST * 2)     // 9216 bytes per part
#define NPART 2                    // Kh, Vh (both fp16)
#define BUF_B   (NPART * TILE_B)   // 18432
#define NBUF 3
#define ZBUF_OFF (NBUF * BUF_B)    // 55296
#define INVZ_OFF (ZBUF_OFF + 512)
#define SMEM_TOTAL (INVZ_OFF + 256)

#define NELEM (BB * HH * SS * DD)  // 8388608
#define MWORDS (BB * SS * (SS / 32))  // 524288 uint32

__device__ uint16_t g_kh[NELEM];
__device__ uint16_t g_vh[NELEM];
__device__ uint32_t g_mbits[MWORDS];

// ---------------- fast 2^y via MUFU.EX2 (1 instr) ----------------
__device__ __forceinline__ float fexp2f(float y) {
    float r;
    asm("ex2.approx.f32 %0, %1;" : "=f"(r) : "f"(y));
    return r;
}
#define L2E  1.4426950408889634f
#define SHL2 11.541560327111707f   // 8*log2(e):  exp(s-8) = 2^(s*L2E - SHL2)

// ---------------- wrappers ----------------
__device__ __forceinline__ void mma16816h(float* c, const uint32_t* a, uint32_t b0, uint32_t b1) {
    asm volatile(
        "mma.sync.aligned.m16n8k16.row.col.f32.f16.f16.f32 "
        "{%0,%1,%2,%3},{%4,%5,%6,%7},{%8,%9},{%0,%1,%2,%3};"
        : "+f"(c[0]), "+f"(c[1]), "+f"(c[2]), "+f"(c[3])
        : "r"(a[0]), "r"(a[1]), "r"(a[2]), "r"(a[3]), "r"(b0), "r"(b1));
}
__device__ __forceinline__ void ldsm_x2_trans(uint32_t& r0, uint32_t& r1, uint32_t addr) {
    asm volatile("ldmatrix.sync.aligned.m8n8.x2.trans.shared.b16 {%0,%1}, [%2];"
                 : "=r"(r0), "=r"(r1) : "r"(addr));
}
__device__ __forceinline__ void ldsm_x4(uint32_t& r0, uint32_t& r1, uint32_t& r2, uint32_t& r3,
                                        uint32_t addr) {
    asm volatile("ldmatrix.sync.aligned.m8n8.x4.shared.b16 {%0,%1,%2,%3}, [%4];"
                 : "=r"(r0), "=r"(r1), "=r"(r2), "=r"(r3) : "r"(addr));
}
__device__ __forceinline__ uint32_t pack_f16(float x, float y) {
    __half2 h = __floats2half2_rn(x, y);
    return *(uint32_t*)&h;
}

__device__ __forceinline__ void cp16(uint32_t dst, const void* src) {
    asm volatile("cp.async.cg.shared.global [%0], [%1], 16;" :: "r"(dst), "l"(src));
}
#define CP_COMMIT() asm volatile("cp.async.commit_group;" ::: "memory")
#define CP_WAIT(n)  asm volatile("cp.async.wait_group %0;" :: "n"(n) : "memory")

// stage K part only (phase A): 2 x 16B per thread
__device__ __forceinline__ void stage_k_async(uint32_t sbuf, size_t base, int tid) {
    const uint16_t* src = g_kh + base;
    #pragma unroll
    for (int it = 0; it < 2; ++it) {
        int idx = tid + it * NTHREADS;     // 0..511
        int row = idx >> 3;
        int seg = idx & 7;
        cp16(sbuf + row * 144 + seg * 16, src + row * 64 + seg * 8);
    }
}
// stage K+V (phase B): 4 x 16B per thread
__device__ __forceinline__ void stage_kv_async(uint32_t sbuf, size_t base, int tid) {
    const uint16_t* srcs[NPART] = {g_kh + base, g_vh + base};
    #pragma unroll
    for (int part = 0; part < NPART; ++part) {
        uint32_t dpart = sbuf + part * TILE_B;
        #pragma unroll
        for (int it = 0; it < 2; ++it) {
            int idx = tid + it * NTHREADS;
            int row = idx >> 3;
            int seg = idx & 7;
            cp16(dpart + row * 144 + seg * 16, srcs[part] + row * 64 + seg * 8);
        }
    }
}

// ---------------- prepack: f32 K,V -> fp16 ----------------
__global__ __launch_bounds__(256)
void prepack_kernel(const float* __restrict__ k, const float* __restrict__ v)
{
    size_t i = (size_t)blockIdx.x * 256 + threadIdx.x;   // float4 index
    float4 x = ((const float4*)k)[i];
    ((uint2*)g_kh)[i] = make_uint2(pack_f16(x.x, x.y), pack_f16(x.z, x.w));
    float4 y = ((const float4*)v)[i];
    ((uint2*)g_vh)[i] = make_uint2(pack_f16(y.x, y.y), pack_f16(y.z, y.w));
}

// ---------------- maskpack: int32 mask -> bitmask ----------------
__global__ __launch_bounds__(256)
void maskpack_kernel(const int* __restrict__ mask)
{
    size_t i = (size_t)blockIdx.x * 256 + threadIdx.x;
    int m = mask[i];
    uint32_t bits = __ballot_sync(0xffffffffu, m != 0);
    if ((threadIdx.x & 31) == 0) g_mbits[i >> 5] = bits;
}

__global__ __launch_bounds__(NTHREADS, 2)
void psdpa_mma_kernel(const float* __restrict__ q,
                      float* __restrict__ out,
                      float* __restrict__ attn)
{
    extern __shared__ __align__(16) char dsm[];
    float* Zbuf  = (float*)(dsm + ZBUF_OFF);
    float* invZs = (float*)(dsm + INVZ_OFF);
    const uint32_t sbase = (uint32_t)__cvta_generic_to_shared(dsm);

    const int tid  = threadIdx.x;
    const int w    = tid >> 5;
    const int lane = tid & 31;
    const int wr   = w & 3;        // row group (16 rows each)
    const int wc   = w >> 2;       // key-column half (32 keys each)
    const int g    = lane >> 2;
    const int j2   = (lane & 3) << 1;

    const int bh = blockIdx.y;
    const int b  = bh >> 4;
    const int q0 = blockIdx.x * TM;

    const float* qbase = q + ((size_t)bh * SS + q0) * DD;
    const size_t kvbase = (size_t)bh * SS * DD;

    // ---- Q fragments (scaled 1/8), fp16; f32 staging in buffer region ----
    uint32_t qh[4][4];
    {
        float* Qtmp = (float*)dsm;   // 16 KB
        const float4* qg = (const float4*)qbase;
        #pragma unroll
        for (int it = 0; it < 4; ++it) {
            int idx = tid + it * NTHREADS;
            int row = idx >> 4;
            int d4  = (idx & 15) << 2;
            float4 x = qg[idx];
            x.x *= 0.125f; x.y *= 0.125f; x.z *= 0.125f; x.w *= 0.125f;
            *(float4*)(Qtmp + row * DD + d4) = x;
        }
        __syncthreads();
        const int r0 = wr * 16 + g, r1 = r0 + 8;
        #pragma unroll
        for (int ks = 0; ks < 4; ++ks) {
            int d0 = ks * 16 + j2, d1 = d0 + 8;
            float2 x0 = *(float2*)(Qtmp + r0 * DD + d0);
            float2 x1 = *(float2*)(Qtmp + r1 * DD + d0);
            float2 x2 = *(float2*)(Qtmp + r0 * DD + d1);
            float2 x3 = *(float2*)(Qtmp + r1 * DD + d1);
            qh[ks][0] = pack_f16(x0.x, x0.y);
            qh[ks][1] = pack_f16(x1.x, x1.y);
            qh[ks][2] = pack_f16(x2.x, x2.y);
            qh[ks][3] = pack_f16(x3.x, x3.y);
        }
        __syncthreads();   // Qtmp region free before cp.async writes
    }

    const int qrow0 = q0 + wr * 16 + g;
    const int qrow8 = qrow0 + 8;
    const uint32_t* mb0 = g_mbits + ((size_t)b * SS + qrow0) * (SS / 32);
    const uint32_t* mb8 = g_mbits + ((size_t)b * SS + qrow8) * (SS / 32);
    float* arow0 = attn + ((size_t)bh * SS + qrow0) * SS;
    float* arow8 = attn + ((size_t)bh * SS + qrow8) * SS;

    // V frag (ldmatrix trans) per-lane offset within a part
    const int lkey = lane & 15;
    const uint32_t vfrag_off = ((wc * 32 + lkey) * KST) * 2;
    // K frag (ldmatrix non-trans) per-lane offset within a part
    const uint32_t kfrag_off =
        (((wc * 32 + (lane >> 4) * 8 + (lane & 7)) * KST) + ((lane >> 3) & 1) * 8) * 2;

    float Zp0 = 0.0f, Zp1 = 0.0f;

    // ================= PHASE A: Z only (K tiles, QK + exp) =================
    stage_k_async(sbase + 0 * BUF_B, kvbase + 0 * (size_t)KT * DD, tid);
    CP_COMMIT();
    stage_k_async(sbase + 1 * BUF_B, kvbase + 1 * (size_t)KT * DD, tid);
    CP_COMMIT();

    int cur = 0;
    for (int t = 0; t < NTILES; ++t) {
        uint32_t mw0 = mb0[2 * t + wc];
        uint32_t mw8 = mb8[2 * t + wc];

        if (t + 1 < NTILES) { CP_WAIT(1); } else { CP_WAIT(0); }
        __syncthreads();
        if (t + 2 < NTILES) {
            int nb = cur + 2; if (nb >= NBUF) nb -= NBUF;
            stage_k_async(sbase + nb * BUF_B, kvbase + (size_t)(t + 2) * KT * DD, tid);
            CP_COMMIT();
        }

        const uint32_t kh_b = sbase + cur * BUF_B + kfrag_off;

        float S[4][4];
        #pragma unroll
        for (int i = 0; i < 4; ++i)
            #pragma unroll
            for (int c = 0; c < 4; ++c) S[i][c] = 0.0f;

        #pragma unroll
        for (int ks = 0; ks < 4; ++ks) {
            uint32_t bh0[4], bh1[4];
            ldsm_x4(bh0[0], bh1[0], bh0[1], bh1[1], kh_b + ks * 32);
            ldsm_x4(bh0[2], bh1[2], bh0[3], bh1[3], kh_b + ks * 32 + 16 * KST * 2);
            #pragma unroll
            for (int n8 = 0; n8 < 4; ++n8) mma16816h(S[n8], qh[ks], bh0[n8], bh1[n8]);
        }

        #pragma unroll
        for (int gi = 0; gi < 4; ++gi) {
            int bit = gi * 8 + j2;
            float e0 = ((mw0 >> bit) & 1)       ? fexp2f(fmaf(S[gi][0], L2E, -SHL2)) : 0.0f;
            float e1 = ((mw0 >> (bit + 1)) & 1) ? fexp2f(fmaf(S[gi][1], L2E, -SHL2)) : 0.0f;
            float e2 = ((mw8 >> bit) & 1)       ? fexp2f(fmaf(S[gi][2], L2E, -SHL2)) : 0.0f;
            float e3 = ((mw8 >> (bit + 1)) & 1) ? fexp2f(fmaf(S[gi][3], L2E, -SHL2)) : 0.0f;
            Zp0 += e0 + e1;
            Zp1 += e2 + e3;
        }

        if (++cur == NBUF) cur = 0;
    }

    // ---- Z reduce -> invZ ----
    Zp0 += __shfl_xor_sync(0xffffffffu, Zp0, 1);
    Zp0 += __shfl_xor_sync(0xffffffffu, Zp0, 2);
    Zp1 += __shfl_xor_sync(0xffffffffu, Zp1, 1);
    Zp1 += __shfl_xor_sync(0xffffffffu, Zp1, 2);
    __syncthreads();
    if ((lane & 3) == 0) {
        Zbuf[wc * TM + wr * 16 + g]     = Zp0;
        Zbuf[wc * TM + wr * 16 + g + 8] = Zp1;
    }
    __syncthreads();
    if (tid < TM) {
        invZs[tid] = 1.0f / (Zbuf[tid] + Zbuf[TM + tid]);
    }
    __syncthreads();
    const float izA = invZs[wr * 16 + g];
    const float izB = invZs[wr * 16 + g + 8];

    // ================= PHASE B: recompute + normalized attn + PV =============
    stage_kv_async(sbase + 0 * BUF_B, kvbase + 0 * (size_t)KT * DD, tid);
    CP_COMMIT();
    stage_kv_async(sbase + 1 * BUF_B, kvbase + 1 * (size_t)KT * DD, tid);
    CP_COMMIT();

    float O[8][4];
    #pragma unroll
    for (int i = 0; i < 8; ++i)
        #pragma unroll
        for (int c = 0; c < 4; ++c) O[i][c] = 0.0f;

    cur = 0;
    for (int t = 0; t < NTILES; ++t) {
        uint32_t mw0 = mb0[2 * t + wc];
        uint32_t mw8 = mb8[2 * t + wc];

        if (t + 1 < NTILES) { CP_WAIT(1); } else { CP_WAIT(0); }
        __syncthreads();
        if (t + 2 < NTILES) {
            int nb = cur + 2; if (nb >= NBUF) nb -= NBUF;
            stage_kv_async(sbase + nb * BUF_B, kvbase + (size_t)(t + 2) * KT * DD, tid);
            CP_COMMIT();
        }

        const uint32_t kh_b = sbase + cur * BUF_B + kfrag_off;
        const uint32_t vh_base = sbase + cur * BUF_B + TILE_B + vfrag_off;

        // ---------------- QK^T (fp16) ----------------
        float S[4][4];
        #pragma unroll
        for (int i = 0; i < 4; ++i)
            #pragma unroll
            for (int c = 0; c < 4; ++c) S[i][c] = 0.0f;

        #pragma unroll
        for (int ks = 0; ks < 4; ++ks) {
            uint32_t bh0[4], bh1[4];
            ldsm_x4(bh0[0], bh1[0], bh0[1], bh1[1], kh_b + ks * 32);
            ldsm_x4(bh0[2], bh1[2], bh0[3], bh1[3], kh_b + ks * 32 + 16 * KST * 2);
            #pragma unroll
            for (int n8 = 0; n8 < 4; ++n8) mma16816h(S[n8], qh[ks], bh0[n8], bh1[n8]);
        }

        // -------- mask + exp + NORMALIZED attn store + P frags --------
        uint32_t phi[2][4];
        #pragma unroll
        for (int gi = 0; gi < 4; ++gi) {
            int cb = t * KT + wc * 32 + gi * 8 + j2;
            int bit = gi * 8 + j2;
            float e0 = ((mw0 >> bit) & 1)       ? fexp2f(fmaf(S[gi][0], L2E, -SHL2)) : 0.0f;
            float e1 = ((mw0 >> (bit + 1)) & 1) ? fexp2f(fmaf(S[gi][1], L2E, -SHL2)) : 0.0f;
            float e2 = ((mw8 >> bit) & 1)       ? fexp2f(fmaf(S[gi][2], L2E, -SHL2)) : 0.0f;
            float e3 = ((mw8 >> (bit + 1)) & 1) ? fexp2f(fmaf(S[gi][3], L2E, -SHL2)) : 0.0f;
            *(float2*)(arow0 + cb) = make_float2(e0 * izA, e1 * izA);
            *(float2*)(arow8 + cb) = make_float2(e2 * izB, e3 * izB);
            int kc = gi >> 1, hh = (gi & 1) << 1;
            phi[kc][hh + 0] = pack_f16(e0, e1);
            phi[kc][hh + 1] = pack_f16(e2, e3);
        }

        // ---------------- P @ V (fp16 x fp16) ----------------
        #pragma unroll
        for (int kc = 0; kc < 2; ++kc) {
            #pragma unroll
            for (int dn8 = 0; dn8 < 8; ++dn8) {
                uint32_t vh0, vh1;
                ldsm_x2_trans(vh0, vh1, vh_base + (kc * 16 * KST + dn8 * 8) * 2);
                mma16816h(O[dn8], phi[kc], vh0, vh1);
            }
        }

        if (++cur == NBUF) cur = 0;
    }

    // ---------------- O reduce + write out ----------------
    __syncthreads();              // all tiles done using smem buffers
    float* Obuf = (float*)dsm;    // [64][68] f32 = 17408 B
    const int r0 = wr * 16 + g, r1 = r0 + 8;
    if (wc == 0) {
        #pragma unroll
        for (int dn8 = 0; dn8 < 8; ++dn8) {
            *(float2*)(Obuf + r0 * 68 + dn8 * 8 + j2) = make_float2(O[dn8][0], O[dn8][1]);
            *(float2*)(Obuf + r1 * 68 + dn8 * 8 + j2) = make_float2(O[dn8][2], O[dn8][3]);
        }
    }
    __syncthreads();
    if (wc == 1) {
        #pragma unroll
        for (int dn8 = 0; dn8 < 8; ++dn8) {
            float2* p0 = (float2*)(Obuf + r0 * 68 + dn8 * 8 + j2);
            float2* p1 = (float2*)(Obuf + r1 * 68 + dn8 * 8 + j2);
            float2 a0 = *p0, a1 = *p1;
            a0.x += O[dn8][0]; a0.y += O[dn8][1];
            a1.x += O[dn8][2]; a1.y += O[dn8][3];
            *p0 = a0; *p1 = a1;
        }
    }
    __syncthreads();
    {
        int row = tid >> 2;
        int dq  = (tid & 3) * 16;
        float iz = invZs[row];
        float* orow = out + ((size_t)bh * SS + q0 + row) * DD + dq;
        #pragma unroll
        for (int i = 0; i < 4; ++i) {
            float4 x = *(float4*)(Obuf + row * 68 + dq + i * 4);
            x.x *= iz; x.y *= iz; x.z *= iz; x.w *= iz;
            *(float4*)(orow + i * 4) = x;
        }
    }
}

extern "C" void kernel_launch(void* const* d_in, const int* in_sizes, int n_in,
                              void* d_out, int out_size)
{
    const float* q    = (const float*)d_in[0];
    const float* k    = (const float*)d_in[1];
    const float* v    = (const float*)d_in[2];
    const int*   mask = (const int*)d_in[3];

    float* out  = (float*)d_out;
    float* attn = out + (size_t)BB * HH * SS * DD;

    static bool configured = false;
    if (!configured) {
        cudaFuncSetAttribute(psdpa_mma_kernel,
                             cudaFuncAttributeMaxDynamicSharedMemorySize, SMEM_TOTAL);
        configured = true;
    }

    prepack_kernel<<<NELEM / 4 / 256, 256>>>(k, v);
    maskpack_kernel<<<(BB * SS * SS) / 256, 256>>>(mask);

    dim3 grid1(SS / TM, BB * HH);
    psdpa_mma_kernel<<<grid1, NTHREADS, SMEM_TOTAL>>>(q, out, attn);
}

// round 15
// speedup vs baseline: 1.5244x; 1.1492x over previous
#include <cuda_runtime.h>
#include <cuda_bf16.h>
#include <cuda_fp16.h>
#include <cstdint>

#define BB 4
#define HH 16
#define SS 2048
#define DD 64

#define TM 128         // q rows per CTA (each warp: 16 rows x full key width)
#define KT 64          // keys per tile
#define NTILES (SS / KT)
#define NTHREADS 256
#define KST 72         // smem row stride in halves (144B)

#define TILE_B  (KT * KST * 2)     // 9216 bytes per part
#define NPART 2                    // Kh, Vh
#define BUF_B   (NPART * TILE_B)   // 18432
#define NBUF 3
#define SMEM_TOTAL (NBUF * BUF_B + 64)   // 55360

#define NELEM (BB * HH * SS * DD)
#define MWORDS (BB * SS * (SS / 32))

__device__ uint16_t g_kh[NELEM];
__device__ uint16_t g_vh[NELEM];
__device__ uint32_t g_mbits[MWORDS];

__device__ __forceinline__ float fexp2f(float y) {
    float r;
    asm("ex2.approx.f32 %0, %1;" : "=f"(r) : "f"(y));
    return r;
}
#define L2E  1.4426950408889634f
#define SHL2 11.541560327111707f   // 8*log2(e)

__device__ __forceinline__ void mma16816h(float* c, const uint32_t* a, uint32_t b0, uint32_t b1) {
    asm volatile(
        "mma.sync.aligned.m16n8k16.row.col.f32.f16.f16.f32 "
        "{%0,%1,%2,%3},{%4,%5,%6,%7},{%8,%9},{%0,%1,%2,%3};"
        : "+f"(c[0]), "+f"(c[1]), "+f"(c[2]), "+f"(c[3])
        : "r"(a[0]), "r"(a[1]), "r"(a[2]), "r"(a[3]), "r"(b0), "r"(b1));
}
__device__ __forceinline__ void ldsm_x2_trans(uint32_t& r0, uint32_t& r1, uint32_t addr) {
    asm volatile("ldmatrix.sync.aligned.m8n8.x2.trans.shared.b16 {%0,%1}, [%2];"
                 : "=r"(r0), "=r"(r1) : "r"(addr));
}
__device__ __forceinline__ void ldsm_x4(uint32_t& r0, uint32_t& r1, uint32_t& r2, uint32_t& r3,
                                        uint32_t addr) {
    asm volatile("ldmatrix.sync.aligned.m8n8.x4.shared.b16 {%0,%1,%2,%3}, [%4];"
                 : "=r"(r0), "=r"(r1), "=r"(r2), "=r"(r3) : "r"(addr));
}
__device__ __forceinline__ uint32_t pack_f16(float x, float y) {
    __half2 h = __floats2half2_rn(x, y);
    return *(uint32_t*)&h;
}

__device__ __forceinline__ void cp16(uint32_t dst, const void* src) {
    asm volatile("cp.async.cg.shared.global [%0], [%1], 16;" :: "r"(dst), "l"(src));
}
#define CP_COMMIT() asm volatile("cp.async.commit_group;" ::: "memory")
#define CP_WAIT(n)  asm volatile("cp.async.wait_group %0;" :: "n"(n) : "memory")

__device__ __forceinline__ void stage_k_async(uint32_t sbuf, size_t base, int tid) {
    const uint16_t* src = g_kh + base;
    #pragma unroll
    for (int it = 0; it < 2; ++it) {
        int idx = tid + it * NTHREADS;
        int row = idx >> 3;
        int seg = idx & 7;
        cp16(sbuf + row * 144 + seg * 16, src + row * 64 + seg * 8);
    }
}
__device__ __forceinline__ void stage_kv_async(uint32_t sbuf, size_t base, int tid) {
    const uint16_t* srcs[NPART] = {g_kh + base, g_vh + base};
    #pragma unroll
    for (int part = 0; part < NPART; ++part) {
        uint32_t dpart = sbuf + part * TILE_B;
        #pragma unroll
        for (int it = 0; it < 2; ++it) {
            int idx = tid + it * NTHREADS;
            int row = idx >> 3;
            int seg = idx & 7;
            cp16(dpart + row * 144 + seg * 16, srcs[part] + row * 64 + seg * 8);
        }
    }
}

__global__ __launch_bounds__(256)
void prepack_kernel(const float* __restrict__ k, const float* __restrict__ v)
{
    size_t i = (size_t)blockIdx.x * 256 + threadIdx.x;
    float4 x = ((const float4*)k)[i];
    ((uint2*)g_kh)[i] = make_uint2(pack_f16(x.x, x.y), pack_f16(x.z, x.w));
    float4 y = ((const float4*)v)[i];
    ((uint2*)g_vh)[i] = make_uint2(pack_f16(y.x, y.y), pack_f16(y.z, y.w));
}

__global__ __launch_bounds__(256)
void maskpack_kernel(const int* __restrict__ mask)
{
    size_t i = (size_t)blockIdx.x * 256 + threadIdx.x;
    int m = mask[i];
    uint32_t bits = __ballot_sync(0xffffffffu, m != 0);
    if ((threadIdx.x & 31) == 0) g_mbits[i >> 5] = bits;
}

__global__ __launch_bounds__(NTHREADS, 2)
void psdpa_mma_kernel(const float* __restrict__ q,
                      float* __restrict__ out,
                      float* __restrict__ attn)
{
    extern __shared__ __align__(16) char dsm[];
    const uint32_t sbase = (uint32_t)__cvta_generic_to_shared(dsm);

    const int tid  = threadIdx.x;
    const int w    = tid >> 5;     // warp owns rows w*16 .. w*16+15
    const int lane = tid & 31;
    const int g    = lane >> 2;
    const int j2   = (lane & 3) << 1;

    const int bh = blockIdx.y;
    const int b  = bh >> 4;
    const int q0 = blockIdx.x * TM;

    const float* qbase = q + ((size_t)bh * SS + q0) * DD;
    const size_t kvbase = (size_t)bh * SS * DD;

    // ---- Q fragments (scaled 1/8), fp16; f32 staging in buffer region ----
    uint32_t qh[4][4];
    {
        float* Qtmp = (float*)dsm;   // 32 KB (fits 55 KB buffer region)
        const float4* qg = (const float4*)qbase;
        #pragma unroll
        for (int it = 0; it < 8; ++it) {
            int idx = tid + it * NTHREADS;
            int row = idx >> 4;
            int d4  = (idx & 15) << 2;
            float4 x = qg[idx];
            x.x *= 0.125f; x.y *= 0.125f; x.z *= 0.125f; x.w *= 0.125f;
            *(float4*)(Qtmp + row * DD + d4) = x;
        }
        __syncthreads();
        const int r0 = w * 16 + g, r1 = r0 + 8;
        #pragma unroll
        for (int ks = 0; ks < 4; ++ks) {
            int d0 = ks * 16 + j2, d1 = d0 + 8;
            float2 x0 = *(float2*)(Qtmp + r0 * DD + d0);
            float2 x1 = *(float2*)(Qtmp + r1 * DD + d0);
            float2 x2 = *(float2*)(Qtmp + r0 * DD + d1);
            float2 x3 = *(float2*)(Qtmp + r1 * DD + d1);
            qh[ks][0] = pack_f16(x0.x, x0.y);
            qh[ks][1] = pack_f16(x1.x, x1.y);
            qh[ks][2] = pack_f16(x2.x, x2.y);
            qh[ks][3] = pack_f16(x3.x, x3.y);
        }
        __syncthreads();
    }

    const int qrow0 = q0 + w * 16 + g;
    const int qrow8 = qrow0 + 8;
    const uint32_t* mb0 = g_mbits + ((size_t)b * SS + qrow0) * (SS / 32);
    const uint32_t* mb8 = g_mbits + ((size_t)b * SS + qrow8) * (SS / 32);
    float* arow0 = attn + ((size_t)bh * SS + qrow0) * SS;
    float* arow8 = attn + ((size_t)bh * SS + qrow8) * SS;

    const int lkey = lane & 15;
    const uint32_t vfrag_off = (lkey * KST) * 2;
    const uint32_t kfrag_off =
        ((((lane >> 4) * 8 + (lane & 7)) * KST) + ((lane >> 3) & 1) * 8) * 2;
    const uint32_t half_off = 32 * KST * 2;   // +32 keys

    float Zp0 = 0.0f, Zp1 = 0.0f;

    // ================= PHASE A: Z only =================
    stage_k_async(sbase + 0 * BUF_B, kvbase, tid);
    CP_COMMIT();
    stage_k_async(sbase + 1 * BUF_B, kvbase + (size_t)KT * DD, tid);
    CP_COMMIT();

    int cur = 0;
    for (int t = 0; t < NTILES; ++t) {
        uint2 mwp0 = *(const uint2*)(mb0 + 2 * t);
        uint2 mwp8 = *(const uint2*)(mb8 + 2 * t);

        if (t + 1 < NTILES) { CP_WAIT(1); } else { CP_WAIT(0); }
        __syncthreads();
        if (t + 2 < NTILES) {
            int nb = cur + 2; if (nb >= NBUF) nb -= NBUF;
            stage_k_async(sbase + nb * BUF_B, kvbase + (size_t)(t + 2) * KT * DD, tid);
            CP_COMMIT();
        }

        #pragma unroll
        for (int h = 0; h < 2; ++h) {
            const uint32_t kh_b = sbase + cur * BUF_B + kfrag_off + h * half_off;
            uint32_t mw0 = h ? mwp0.y : mwp0.x;
            uint32_t mw8 = h ? mwp8.y : mwp8.x;

            float S[4][4];
            #pragma unroll
            for (int i = 0; i < 4; ++i)
                #pragma unroll
                for (int c = 0; c < 4; ++c) S[i][c] = 0.0f;

            #pragma unroll
            for (int ks = 0; ks < 4; ++ks) {
                uint32_t bh0[4], bh1[4];
                ldsm_x4(bh0[0], bh1[0], bh0[1], bh1[1], kh_b + ks * 32);
                ldsm_x4(bh0[2], bh1[2], bh0[3], bh1[3], kh_b + ks * 32 + 16 * KST * 2);
                #pragma unroll
                for (int n8 = 0; n8 < 4; ++n8) mma16816h(S[n8], qh[ks], bh0[n8], bh1[n8]);
            }

            #pragma unroll
            for (int gi = 0; gi < 4; ++gi) {
                int bit = gi * 8 + j2;
                float e0 = ((mw0 >> bit) & 1)       ? fexp2f(fmaf(S[gi][0], L2E, -SHL2)) : 0.0f;
                float e1 = ((mw0 >> (bit + 1)) & 1) ? fexp2f(fmaf(S[gi][1], L2E, -SHL2)) : 0.0f;
                float e2 = ((mw8 >> bit) & 1)       ? fexp2f(fmaf(S[gi][2], L2E, -SHL2)) : 0.0f;
                float e3 = ((mw8 >> (bit + 1)) & 1) ? fexp2f(fmaf(S[gi][3], L2E, -SHL2)) : 0.0f;
                Zp0 += e0 + e1;
                Zp1 += e2 + e3;
            }
        }
        if (++cur == NBUF) cur = 0;
    }

    // ---- Z reduce within quad (full row owned by this warp) ----
    Zp0 += __shfl_xor_sync(0xffffffffu, Zp0, 1);
    Zp0 += __shfl_xor_sync(0xffffffffu, Zp0, 2);
    Zp1 += __shfl_xor_sync(0xffffffffu, Zp1, 1);
    Zp1 += __shfl_xor_sync(0xffffffffu, Zp1, 2);
    const float izA = 1.0f / Zp0;
    const float izB = 1.0f / Zp1;
    __syncthreads();   // all warps done reading phase-A buffers

    // ================= PHASE B: recompute + normalized attn + PV =============
    stage_kv_async(sbase + 0 * BUF_B, kvbase, tid);
    CP_COMMIT();
    stage_kv_async(sbase + 1 * BUF_B, kvbase + (size_t)KT * DD, tid);
    CP_COMMIT();

    float O[8][4];
    #pragma unroll
    for (int i = 0; i < 8; ++i)
        #pragma unroll
        for (int c = 0; c < 4; ++c) O[i][c] = 0.0f;

    cur = 0;
    for (int t = 0; t < NTILES; ++t) {
        uint2 mwp0 = *(const uint2*)(mb0 + 2 * t);
        uint2 mwp8 = *(const uint2*)(mb8 + 2 * t);

        if (t + 1 < NTILES) { CP_WAIT(1); } else { CP_WAIT(0); }
        __syncthreads();
        if (t + 2 < NTILES) {
            int nb = cur + 2; if (nb >= NBUF) nb -= NBUF;
            stage_kv_async(sbase + nb * BUF_B, kvbase + (size_t)(t + 2) * KT * DD, tid);
            CP_COMMIT();
        }

        #pragma unroll
        for (int h = 0; h < 2; ++h) {
            const uint32_t kh_b = sbase + cur * BUF_B + kfrag_off + h * half_off;
            const uint32_t vh_base = sbase + cur * BUF_B + TILE_B + vfrag_off + h * half_off;
            uint32_t mw0 = h ? mwp0.y : mwp0.x;
            uint32_t mw8 = h ? mwp8.y : mwp8.x;

            float S[4][4];
            #pragma unroll
            for (int i = 0; i < 4; ++i)
                #pragma unroll
                for (int c = 0; c < 4; ++c) S[i][c] = 0.0f;

            #pragma unroll
            for (int ks = 0; ks < 4; ++ks) {
                uint32_t bh0[4], bh1[4];
                ldsm_x4(bh0[0], bh1[0], bh0[1], bh1[1], kh_b + ks * 32);
                ldsm_x4(bh0[2], bh1[2], bh0[3], bh1[3], kh_b + ks * 32 + 16 * KST * 2);
                #pragma unroll
                for (int n8 = 0; n8 < 4; ++n8) mma16816h(S[n8], qh[ks], bh0[n8], bh1[n8]);
            }

            uint32_t phi[2][4];
            #pragma unroll
            for (int gi = 0; gi < 4; ++gi) {
                int cb = t * KT + h * 32 + gi * 8 + j2;
                int bit = gi * 8 + j2;
                float e0 = ((mw0 >> bit) & 1)       ? fexp2f(fmaf(S[gi][0], L2E, -SHL2)) : 0.0f;
                float e1 = ((mw0 >> (bit + 1)) & 1) ? fexp2f(fmaf(S[gi][1], L2E, -SHL2)) : 0.0f;
                float e2 = ((mw8 >> bit) & 1)       ? fexp2f(fmaf(S[gi][2], L2E, -SHL2)) : 0.0f;
                float e3 = ((mw8 >> (bit + 1)) & 1) ? fexp2f(fmaf(S[gi][3], L2E, -SHL2)) : 0.0f;
                *(float2*)(arow0 + cb) = make_float2(e0 * izA, e1 * izA);
                *(float2*)(arow8 + cb) = make_float2(e2 * izB, e3 * izB);
                int kc = gi >> 1, hh = (gi & 1) << 1;
                phi[kc][hh + 0] = pack_f16(e0, e1);
                phi[kc][hh + 1] = pack_f16(e2, e3);
            }

            #pragma unroll
            for (int kc = 0; kc < 2; ++kc) {
                #pragma unroll
                for (int dn8 = 0; dn8 < 8; ++dn8) {
                    uint32_t vh0, vh1;
                    ldsm_x2_trans(vh0, vh1, vh_base + (kc * 16 * KST + dn8 * 8) * 2);
                    mma16816h(O[dn8], phi[kc], vh0, vh1);
                }
            }
        }
        if (++cur == NBUF) cur = 0;
    }

    // ---------------- O write (warp-local, direct from registers) ----------------
    {
        float* orow0 = out + ((size_t)bh * SS + qrow0) * DD;
        float* orow8 = out + ((size_t)bh * SS + qrow8) * DD;
        #pragma unroll
        for (int dn8 = 0; dn8 < 8; ++dn8) {
            *(float2*)(orow0 + dn8 * 8 + j2) = make_float2(O[dn8][0] * izA, O[dn8][1] * izA);
            *(float2*)(orow8 + dn8 * 8 + j2) = make_float2(O[dn8][2] * izB, O[dn8][3] * izB);
        }
    }
}

extern "C" void kernel_launch(void* const* d_in, const int* in_sizes, int n_in,
                              void* d_out, int out_size)
{
    const float* q    = (const float*)d_in[0];
    const float* k    = (const float*)d_in[1];
    const float* v    = (const float*)d_in[2];
    const int*   mask = (const int*)d_in[3];

    float* out  = (float*)d_out;
    float* attn = out + (size_t)BB * HH * SS * DD;

    static bool configured = false;
    if (!configured) {
        cudaFuncSetAttribute(psdpa_mma_kernel,
                             cudaFuncAttributeMaxDynamicSharedMemorySize, SMEM_TOTAL);
        configured = true;
    }

    prepack_kernel<<<NELEM / 4 / 256, 256>>>(k, v);
    maskpack_kernel<<<(BB * SS * SS) / 256, 256>>>(mask);

    dim3 grid1(SS / TM, BB * HH);
    psdpa_mma_kernel<<<grid1, NTHREADS, SMEM_TOTAL>>>(q, out, attn);
}